// round 13
// baseline (speedup 1.0000x reference)
#include <cuda_runtime.h>
#include <cuda_bf16.h>

#define NN 8192
#define BB 2
#define COLS_PER_BLOCK 1024   // 256 threads * float4, single strip
#define ROWS_PER_BLOCK 64
#define GRID_X (NN / COLS_PER_BLOCK)   // 8
#define GRID_Y (NN / ROWS_PER_BLOCK)   // 128
#define NBLOCKS (GRID_X * GRID_Y)      // 1024 -> ~whole grid resident, 55 warps/SM

// Scratch (allocation-free rule: __device__ globals)
__device__ float g_deg[NN];
__device__ float g_z[BB * NN];
__device__ float g_sums[BB];
__device__ unsigned int g_done;

// ---------------------------------------------------------------------------
// K1: column sums  deg[c] = sum_r DSM[r,c].  Streaming loads (__ldcs):
// DSM (268MB) has zero reuse across its two passes (L2 is 126MB).
// Occupancy-first geometry: 1024 small blocks so the full grid is resident
// in one wave (~55 warps/SM of outstanding LDG.128).
// Side work (free under the stream): zero g_z, fill action_prob out with
// 1.0f (softmax over a size-1 axis is exactly 1). 1024 blocks * 16 = 16384.
// ---------------------------------------------------------------------------
__global__ void __launch_bounds__(256) colsum_kernel(const float* __restrict__ dsm,
                                                     float* __restrict__ out,
                                                     int out_size) {
    const int t   = threadIdx.x;
    const int bid = blockIdx.y * GRID_X + blockIdx.x;    // 0..1023

    // Distributed side-init: each block owns 16 elements of g_z and out.
    if (t < 16) {
        g_z[bid * 16 + t] = 0.0f;
    } else if (t < 32) {
        int i = bid * 16 + (t - 16);
        if (i < out_size) out[i] = 1.0f;
    }

    const int c0 = blockIdx.x * COLS_PER_BLOCK + t * 4;
    const int r0 = blockIdx.y * ROWS_PER_BLOCK;

    float ax = 0.f, ay = 0.f, az = 0.f, aw = 0.f;
    const float4* p = (const float4*)(dsm + (size_t)r0 * NN + c0);
    #pragma unroll 8
    for (int r = 0; r < ROWS_PER_BLOCK; ++r) {
        float4 v = __ldcs(p);
        ax += v.x; ay += v.y; az += v.z; aw += v.w;
        p += NN / 4;
    }
    atomicAdd(&g_deg[c0 + 0], ax);
    atomicAdd(&g_deg[c0 + 1], ay);
    atomicAdd(&g_deg[c0 + 2], az);
    atomicAdd(&g_deg[c0 + 3], aw);
}

// ---------------------------------------------------------------------------
// K2: z[b,c] = sum_r (dinv[r]*x[b,r]) * DSM[r,c]  for b = 0,1 in one pass.
// Same occupancy-first geometry as colsum.
// ---------------------------------------------------------------------------
__global__ void __launch_bounds__(256) matvec_kernel(const float* __restrict__ dsm,
                                                     const float* __restrict__ x) {
    __shared__ float s0[ROWS_PER_BLOCK];
    __shared__ float s1[ROWS_PER_BLOCK];

    const int r0 = blockIdx.y * ROWS_PER_BLOCK;
    const int t  = threadIdx.x;

    // Stage dinv[r]*x[b,r] for this row chunk (2*64 = 128 values)
    if (t < 2 * ROWS_PER_BLOCK) {
        int b = t / ROWS_PER_BLOCK;      // 0 or 1
        int i = t % ROWS_PER_BLOCK;
        float d  = g_deg[r0 + i];
        float di = (d > 0.f) ? rsqrtf(d) : 0.f;
        float v  = di * x[b * NN + r0 + i];
        if (b == 0) s0[i] = v; else s1[i] = v;
    }
    __syncthreads();

    const int c0 = blockIdx.x * COLS_PER_BLOCK + t * 4;
    float a0x = 0.f, a0y = 0.f, a0z = 0.f, a0w = 0.f;
    float a1x = 0.f, a1y = 0.f, a1z = 0.f, a1w = 0.f;

    const float4* p = (const float4*)(dsm + (size_t)r0 * NN + c0);
    #pragma unroll 8
    for (int r = 0; r < ROWS_PER_BLOCK; ++r) {
        float4 v = __ldcs(p);
        float w0 = s0[r];
        float w1v = s1[r];
        a0x += v.x * w0;  a0y += v.y * w0;  a0z += v.z * w0;  a0w += v.w * w0;
        a1x += v.x * w1v; a1y += v.y * w1v; a1z += v.z * w1v; a1w += v.w * w1v;
        p += NN / 4;
    }
    atomicAdd(&g_z[c0 + 0], a0x);
    atomicAdd(&g_z[c0 + 1], a0y);
    atomicAdd(&g_z[c0 + 2], a0z);
    atomicAdd(&g_z[c0 + 3], a0w);
    atomicAdd(&g_z[NN + c0 + 0], a1x);
    atomicAdd(&g_z[NN + c0 + 1], a1y);
    atomicAdd(&g_z[NN + c0 + 2], a1z);
    atomicAdd(&g_z[NN + c0 + 3], a1w);
}

// ---------------------------------------------------------------------------
// K3: fused reduction + final scalar (last-block-done pattern). R9-proven.
// 32 blocks x 256 threads = 8192 threads, one column each.
// ---------------------------------------------------------------------------
__global__ void __launch_bounds__(256) reduce_finalize_kernel(
    const float* __restrict__ w1,  const float* __restrict__ b1,
    const float* __restrict__ lw1, const float* __restrict__ lb1,
    const float* __restrict__ lw2, const float* __restrict__ lb2,
    const float* __restrict__ w2,  const float* __restrict__ b2,
    const float* __restrict__ w3,  const float* __restrict__ b3,
    const float* __restrict__ wv,  const float* __restrict__ bv,
    float* __restrict__ out, int out_size)
{
    __shared__ float red0[8];
    __shared__ float red1[8];
    __shared__ bool  last;

    const float W1 = w1[0],  B1 = b1[0];
    const float L1 = lw1[0], LB1 = lb1[0];
    const float L2 = lw2[0], LB2 = lb2[0];

    const int c = blockIdx.x * blockDim.x + threadIdx.x;  // 0..8191 exactly

    float d  = g_deg[c];
    float di = (d > 0.f) ? rsqrtf(d) : 0.f;
    float h0 = fmaxf(g_z[c]      * di * W1 + B1, 0.f);
    float h1 = fmaxf(g_z[NN + c] * di * W1 + B1, 0.f);
    h0 = fmaxf(h0 * L1 + LB1, 0.f);
    h1 = fmaxf(h1 * L1 + LB1, 0.f);
    h0 = fmaxf(h0 * L2 + LB2, 0.f);
    h1 = fmaxf(h1 * L2 + LB2, 0.f);

    for (int o = 16; o > 0; o >>= 1) {
        h0 += __shfl_xor_sync(0xFFFFFFFFu, h0, o);
        h1 += __shfl_xor_sync(0xFFFFFFFFu, h1, o);
    }
    int warp = threadIdx.x >> 5;
    int lane = threadIdx.x & 31;
    if (lane == 0) { red0[warp] = h0; red1[warp] = h1; }
    __syncthreads();

    if (threadIdx.x == 0) {
        float t0 = 0.f, t1 = 0.f;
        #pragma unroll
        for (int w = 0; w < 8; ++w) { t0 += red0[w]; t1 += red1[w]; }
        atomicAdd(&g_sums[0], t0);
        atomicAdd(&g_sums[1], t1);
        __threadfence();
        unsigned int prev = atomicAdd(&g_done, 1u);
        last = (prev == gridDim.x - 1);
    }
    __syncthreads();

    if (last && threadIdx.x == 0 && out_size > BB * NN) {
        const float inv_n = 1.0f / (float)NN;
        float m0 = fmaxf(g_sums[0] * inv_n * w2[0] + b2[0], 0.f);
        float m1 = fmaxf(g_sums[1] * inv_n * w2[0] + b2[0], 0.f);
        float s0v = fmaxf(m0 * w3[0] + b3[0], 0.f);
        float s1v = fmaxf(m1 * w3[0] + b3[0], 0.f);
        float v   = fmaxf(s0v, s1v);
        out[BB * NN] = v * wv[0] + bv[0];
    }
}

// ---------------------------------------------------------------------------
extern "C" void kernel_launch(void* const* d_in, const int* in_sizes, int n_in,
                              void* d_out, int out_size) {
    const float* x   = (const float*)d_in[0];
    const float* dsm = (const float*)d_in[1];
    const float* w1  = (const float*)d_in[2];
    const float* b1  = (const float*)d_in[3];
    const float* lw1 = (const float*)d_in[4];
    const float* lb1 = (const float*)d_in[5];
    const float* lw2 = (const float*)d_in[6];
    const float* lb2 = (const float*)d_in[7];
    const float* w2  = (const float*)d_in[8];
    const float* b2  = (const float*)d_in[9];
    const float* w3  = (const float*)d_in[10];
    const float* b3  = (const float*)d_in[11];
    // wa (d_in[12]) / ba (d_in[13]) cancel inside the size-1 softmax
    const float* wv  = (const float*)d_in[14];
    const float* bv  = (const float*)d_in[15];
    float* out = (float*)d_out;

    // Init via memset nodes (graph-capturable; no kernel-launch latency).
    void* p_deg  = nullptr;
    void* p_sums = nullptr;
    void* p_done = nullptr;
    cudaGetSymbolAddress(&p_deg,  g_deg);
    cudaGetSymbolAddress(&p_sums, g_sums);
    cudaGetSymbolAddress(&p_done, g_done);
    cudaMemsetAsync(p_deg,  0, NN * sizeof(float));
    cudaMemsetAsync(p_sums, 0, BB * sizeof(float));
    cudaMemsetAsync(p_done, 0, sizeof(unsigned int));

    dim3 grid(GRID_X, GRID_Y);  // (8, 128) = 1024 blocks
    colsum_kernel<<<grid, 256>>>(dsm, out, out_size);
    matvec_kernel<<<grid, 256>>>(dsm, x);

    reduce_finalize_kernel<<<NN / 256, 256>>>(w1, b1, lw1, lb1, lw2, lb2,
                                              w2, b2, w3, b3, wv, bv, out, out_size);
}

// round 14
// speedup vs baseline: 1.1197x; 1.1197x over previous
#include <cuda_runtime.h>
#include <cuda_bf16.h>

#define NN 8192
#define BB 2
#define COLS_PER_BLOCK 1024   // 256 threads * float4, single strip
#define ROWS_PER_BLOCK 128
#define GRID_X (NN / COLS_PER_BLOCK)   // 8
#define GRID_Y (NN / ROWS_PER_BLOCK)   // 64
#define NBLOCKS (GRID_X * GRID_Y)      // 512  -> ~28 warps/SM, measured optimum

// Scratch (allocation-free rule: __device__ globals)
__device__ float g_deg[NN];
__device__ float g_z[BB * NN];
__device__ float g_sums[BB];
__device__ unsigned int g_done;

// ---------------------------------------------------------------------------
// K1: column sums  deg[c] = sum_r DSM[r,c].  Streaming loads (__ldcs):
// DSM (268MB) has zero reuse across its two passes (L2 is 126MB).
// Geometry (8,64)=512 blocks, ROWS=128: measured optimum (92.2us total in
// R7/R9; 256 and 1024 block variants both regressed).
// Side work (free under the stream): zero g_z, fill action_prob out with
// 1.0f (softmax over a size-1 axis is exactly 1). 512 blocks * 32 = 16384.
// ---------------------------------------------------------------------------
__global__ void __launch_bounds__(256) colsum_kernel(const float* __restrict__ dsm,
                                                     float* __restrict__ out,
                                                     int out_size) {
    const int t   = threadIdx.x;
    const int bid = blockIdx.y * GRID_X + blockIdx.x;    // 0..511

    // Distributed side-init: each block owns 32 elements of g_z and out.
    if (t < 32) {
        g_z[bid * 32 + t] = 0.0f;
    } else if (t < 64) {
        int i = bid * 32 + (t - 32);
        if (i < out_size) out[i] = 1.0f;
    }

    const int c0 = blockIdx.x * COLS_PER_BLOCK + t * 4;
    const int r0 = blockIdx.y * ROWS_PER_BLOCK;

    float ax = 0.f, ay = 0.f, az = 0.f, aw = 0.f;
    const float4* p = (const float4*)(dsm + (size_t)r0 * NN + c0);
    #pragma unroll 8
    for (int r = 0; r < ROWS_PER_BLOCK; ++r) {
        float4 v = __ldcs(p);
        ax += v.x; ay += v.y; az += v.z; aw += v.w;
        p += NN / 4;
    }
    atomicAdd(&g_deg[c0 + 0], ax);
    atomicAdd(&g_deg[c0 + 1], ay);
    atomicAdd(&g_deg[c0 + 2], az);
    atomicAdd(&g_deg[c0 + 3], aw);
}

// ---------------------------------------------------------------------------
// K2: z[b,c] = sum_r (dinv[r]*x[b,r]) * DSM[r,c]  for b = 0,1 in one pass
// ---------------------------------------------------------------------------
__global__ void __launch_bounds__(256) matvec_kernel(const float* __restrict__ dsm,
                                                     const float* __restrict__ x) {
    __shared__ float s0[ROWS_PER_BLOCK];
    __shared__ float s1[ROWS_PER_BLOCK];

    const int r0 = blockIdx.y * ROWS_PER_BLOCK;
    const int t  = threadIdx.x;

    // Stage dinv[r]*x[b,r] for this row chunk (2*128 = 256 values)
    {
        int b = t / ROWS_PER_BLOCK;      // 0 or 1
        int i = t % ROWS_PER_BLOCK;
        float d  = g_deg[r0 + i];
        float di = (d > 0.f) ? rsqrtf(d) : 0.f;
        float v  = di * x[b * NN + r0 + i];
        if (b == 0) s0[i] = v; else s1[i] = v;
    }
    __syncthreads();

    const int c0 = blockIdx.x * COLS_PER_BLOCK + t * 4;
    float a0x = 0.f, a0y = 0.f, a0z = 0.f, a0w = 0.f;
    float a1x = 0.f, a1y = 0.f, a1z = 0.f, a1w = 0.f;

    const float4* p = (const float4*)(dsm + (size_t)r0 * NN + c0);
    #pragma unroll 8
    for (int r = 0; r < ROWS_PER_BLOCK; ++r) {
        float4 v = __ldcs(p);
        float w0 = s0[r];
        float w1v = s1[r];
        a0x += v.x * w0;  a0y += v.y * w0;  a0z += v.z * w0;  a0w += v.w * w0;
        a1x += v.x * w1v; a1y += v.y * w1v; a1z += v.z * w1v; a1w += v.w * w1v;
        p += NN / 4;
    }
    atomicAdd(&g_z[c0 + 0], a0x);
    atomicAdd(&g_z[c0 + 1], a0y);
    atomicAdd(&g_z[c0 + 2], a0z);
    atomicAdd(&g_z[c0 + 3], a0w);
    atomicAdd(&g_z[NN + c0 + 0], a1x);
    atomicAdd(&g_z[NN + c0 + 1], a1y);
    atomicAdd(&g_z[NN + c0 + 2], a1z);
    atomicAdd(&g_z[NN + c0 + 3], a1w);
}

// ---------------------------------------------------------------------------
// K3: fused reduction + final scalar (last-block-done pattern). R9-proven.
// 32 blocks x 256 threads = 8192 threads, one column each.
// ---------------------------------------------------------------------------
__global__ void __launch_bounds__(256) reduce_finalize_kernel(
    const float* __restrict__ w1,  const float* __restrict__ b1,
    const float* __restrict__ lw1, const float* __restrict__ lb1,
    const float* __restrict__ lw2, const float* __restrict__ lb2,
    const float* __restrict__ w2,  const float* __restrict__ b2,
    const float* __restrict__ w3,  const float* __restrict__ b3,
    const float* __restrict__ wv,  const float* __restrict__ bv,
    float* __restrict__ out, int out_size)
{
    __shared__ float red0[8];
    __shared__ float red1[8];
    __shared__ bool  last;

    const float W1 = w1[0],  B1 = b1[0];
    const float L1 = lw1[0], LB1 = lb1[0];
    const float L2 = lw2[0], LB2 = lb2[0];

    const int c = blockIdx.x * blockDim.x + threadIdx.x;  // 0..8191 exactly

    float d  = g_deg[c];
    float di = (d > 0.f) ? rsqrtf(d) : 0.f;
    float h0 = fmaxf(g_z[c]      * di * W1 + B1, 0.f);
    float h1 = fmaxf(g_z[NN + c] * di * W1 + B1, 0.f);
    h0 = fmaxf(h0 * L1 + LB1, 0.f);
    h1 = fmaxf(h1 * L1 + LB1, 0.f);
    h0 = fmaxf(h0 * L2 + LB2, 0.f);
    h1 = fmaxf(h1 * L2 + LB2, 0.f);

    for (int o = 16; o > 0; o >>= 1) {
        h0 += __shfl_xor_sync(0xFFFFFFFFu, h0, o);
        h1 += __shfl_xor_sync(0xFFFFFFFFu, h1, o);
    }
    int warp = threadIdx.x >> 5;
    int lane = threadIdx.x & 31;
    if (lane == 0) { red0[warp] = h0; red1[warp] = h1; }
    __syncthreads();

    if (threadIdx.x == 0) {
        float t0 = 0.f, t1 = 0.f;
        #pragma unroll
        for (int w = 0; w < 8; ++w) { t0 += red0[w]; t1 += red1[w]; }
        atomicAdd(&g_sums[0], t0);
        atomicAdd(&g_sums[1], t1);
        __threadfence();
        unsigned int prev = atomicAdd(&g_done, 1u);
        last = (prev == gridDim.x - 1);
    }
    __syncthreads();

    if (last && threadIdx.x == 0 && out_size > BB * NN) {
        const float inv_n = 1.0f / (float)NN;
        float m0 = fmaxf(g_sums[0] * inv_n * w2[0] + b2[0], 0.f);
        float m1 = fmaxf(g_sums[1] * inv_n * w2[0] + b2[0], 0.f);
        float s0v = fmaxf(m0 * w3[0] + b3[0], 0.f);
        float s1v = fmaxf(m1 * w3[0] + b3[0], 0.f);
        float v   = fmaxf(s0v, s1v);
        out[BB * NN] = v * wv[0] + bv[0];
    }
}

// ---------------------------------------------------------------------------
extern "C" void kernel_launch(void* const* d_in, const int* in_sizes, int n_in,
                              void* d_out, int out_size) {
    const float* x   = (const float*)d_in[0];
    const float* dsm = (const float*)d_in[1];
    const float* w1  = (const float*)d_in[2];
    const float* b1  = (const float*)d_in[3];
    const float* lw1 = (const float*)d_in[4];
    const float* lb1 = (const float*)d_in[5];
    const float* lw2 = (const float*)d_in[6];
    const float* lb2 = (const float*)d_in[7];
    const float* w2  = (const float*)d_in[8];
    const float* b2  = (const float*)d_in[9];
    const float* w3  = (const float*)d_in[10];
    const float* b3  = (const float*)d_in[11];
    // wa (d_in[12]) / ba (d_in[13]) cancel inside the size-1 softmax
    const float* wv  = (const float*)d_in[14];
    const float* bv  = (const float*)d_in[15];
    float* out = (float*)d_out;

    // Init via memset nodes (graph-capturable; cheaper than a 3.8us kernel).
    void* p_deg  = nullptr;
    void* p_sums = nullptr;
    void* p_done = nullptr;
    cudaGetSymbolAddress(&p_deg,  g_deg);
    cudaGetSymbolAddress(&p_sums, g_sums);
    cudaGetSymbolAddress(&p_done, g_done);
    cudaMemsetAsync(p_deg,  0, NN * sizeof(float));
    cudaMemsetAsync(p_sums, 0, BB * sizeof(float));
    cudaMemsetAsync(p_done, 0, sizeof(unsigned int));

    dim3 grid(GRID_X, GRID_Y);  // (8, 64) = 512 blocks
    colsum_kernel<<<grid, 256>>>(dsm, out, out_size);
    matvec_kernel<<<grid, 256>>>(dsm, x);

    reduce_finalize_kernel<<<NN / 256, 256>>>(w1, b1, lw1, lb1, lw2, lb2,
                                              w2, b2, w3, b3, wv, bv, out, out_size);
}

// round 16
// speedup vs baseline: 1.2884x; 1.1507x over previous
#include <cuda_runtime.h>
#include <cuda_bf16.h>

#define NN 8192
#define BB 2
#define COLS_PER_BLOCK 1024   // 256 threads * float4, single strip
#define ROWS_PER_BLOCK 128
#define GRID_X (NN / COLS_PER_BLOCK)   // 8
#define GRID_Y (NN / ROWS_PER_BLOCK)   // 64
#define NBLOCKS (GRID_X * GRID_Y)      // 512  (measured optimum geometry)

// Scratch (allocation-free rule: __device__ globals). Statically zeroed at
// load; reduce_finalize's last block re-zeroes everything it consumed so the
// next graph replay starts from identical state. g_z is re-zeroed by
// colsum's side-init each call.
__device__ float g_deg[NN];
__device__ float g_z[BB * NN];
__device__ float g_sums[BB];
__device__ unsigned int g_done;

// ---------------------------------------------------------------------------
// K1: column sums  deg[c] = sum_r DSM[r,c].  Streaming loads (__ldcs):
// DSM (268MB) has zero reuse across its two passes (L2 is 126MB).
// Geometry (8,64)=512 blocks, ROWS=128: measured optimum (92.2us champion;
// 256-block/2-strip and 1024-block variants both regressed).
// Side work (free under the stream): zero g_z for THIS call's matvec, fill
// action_prob out with 1.0f (softmax over a size-1 axis is exactly 1).
// 512 blocks * 32 = 16384 covers both arrays.
// ---------------------------------------------------------------------------
__global__ void __launch_bounds__(256) colsum_kernel(const float* __restrict__ dsm,
                                                     float* __restrict__ out,
                                                     int out_size) {
    const int t   = threadIdx.x;
    const int bid = blockIdx.y * GRID_X + blockIdx.x;    // 0..511

    // Distributed side-init: each block owns 32 elements of g_z and out.
    if (t < 32) {
        g_z[bid * 32 + t] = 0.0f;
    } else if (t < 64) {
        int i = bid * 32 + (t - 32);
        if (i < out_size) out[i] = 1.0f;
    }

    const int c0 = blockIdx.x * COLS_PER_BLOCK + t * 4;
    const int r0 = blockIdx.y * ROWS_PER_BLOCK;

    float ax = 0.f, ay = 0.f, az = 0.f, aw = 0.f;
    const float4* p = (const float4*)(dsm + (size_t)r0 * NN + c0);
    #pragma unroll 8
    for (int r = 0; r < ROWS_PER_BLOCK; ++r) {
        float4 v = __ldcs(p);
        ax += v.x; ay += v.y; az += v.z; aw += v.w;
        p += NN / 4;
    }
    atomicAdd(&g_deg[c0 + 0], ax);
    atomicAdd(&g_deg[c0 + 1], ay);
    atomicAdd(&g_deg[c0 + 2], az);
    atomicAdd(&g_deg[c0 + 3], aw);
}

// ---------------------------------------------------------------------------
// K2: z[b,c] = sum_r (dinv[r]*x[b,r]) * DSM[r,c]  for b = 0,1 in one pass
// ---------------------------------------------------------------------------
__global__ void __launch_bounds__(256) matvec_kernel(const float* __restrict__ dsm,
                                                     const float* __restrict__ x) {
    __shared__ float s0[ROWS_PER_BLOCK];
    __shared__ float s1[ROWS_PER_BLOCK];

    const int r0 = blockIdx.y * ROWS_PER_BLOCK;
    const int t  = threadIdx.x;

    // Stage dinv[r]*x[b,r] for this row chunk (2*128 = 256 values)
    {
        int b = t / ROWS_PER_BLOCK;      // 0 or 1
        int i = t % ROWS_PER_BLOCK;
        float d  = g_deg[r0 + i];
        float di = (d > 0.f) ? rsqrtf(d) : 0.f;
        float v  = di * x[b * NN + r0 + i];
        if (b == 0) s0[i] = v; else s1[i] = v;
    }
    __syncthreads();

    const int c0 = blockIdx.x * COLS_PER_BLOCK + t * 4;
    float a0x = 0.f, a0y = 0.f, a0z = 0.f, a0w = 0.f;
    float a1x = 0.f, a1y = 0.f, a1z = 0.f, a1w = 0.f;

    const float4* p = (const float4*)(dsm + (size_t)r0 * NN + c0);
    #pragma unroll 8
    for (int r = 0; r < ROWS_PER_BLOCK; ++r) {
        float4 v = __ldcs(p);
        float w0 = s0[r];
        float w1v = s1[r];
        a0x += v.x * w0;  a0y += v.y * w0;  a0z += v.z * w0;  a0w += v.w * w0;
        a1x += v.x * w1v; a1y += v.y * w1v; a1z += v.z * w1v; a1w += v.w * w1v;
        p += NN / 4;
    }
    atomicAdd(&g_z[c0 + 0], a0x);
    atomicAdd(&g_z[c0 + 1], a0y);
    atomicAdd(&g_z[c0 + 2], a0z);
    atomicAdd(&g_z[c0 + 3], a0w);
    atomicAdd(&g_z[NN + c0 + 0], a1x);
    atomicAdd(&g_z[NN + c0 + 1], a1y);
    atomicAdd(&g_z[NN + c0 + 2], a1z);
    atomicAdd(&g_z[NN + c0 + 3], a1w);
}

// ---------------------------------------------------------------------------
// K3: fused reduction + final scalar (last-block-done pattern) + self-clean.
// 32 blocks x 256 threads = 8192 threads, one column each. The last block
// emits the state value, then re-zeroes g_deg / g_sums / g_done so the next
// graph replay starts from the same state (all blocks are provably done
// reading them at that point).
// ---------------------------------------------------------------------------
__global__ void __launch_bounds__(256) reduce_finalize_kernel(
    const float* __restrict__ w1,  const float* __restrict__ b1,
    const float* __restrict__ lw1, const float* __restrict__ lb1,
    const float* __restrict__ lw2, const float* __restrict__ lb2,
    const float* __restrict__ w2,  const float* __restrict__ b2,
    const float* __restrict__ w3,  const float* __restrict__ b3,
    const float* __restrict__ wv,  const float* __restrict__ bv,
    float* __restrict__ out, int out_size)
{
    __shared__ float red0[8];
    __shared__ float red1[8];
    __shared__ bool  last;

    const float W1 = w1[0],  B1 = b1[0];
    const float L1 = lw1[0], LB1 = lb1[0];
    const float L2 = lw2[0], LB2 = lb2[0];

    const int c = blockIdx.x * blockDim.x + threadIdx.x;  // 0..8191 exactly

    float d  = g_deg[c];
    float di = (d > 0.f) ? rsqrtf(d) : 0.f;
    float h0 = fmaxf(g_z[c]      * di * W1 + B1, 0.f);
    float h1 = fmaxf(g_z[NN + c] * di * W1 + B1, 0.f);
    h0 = fmaxf(h0 * L1 + LB1, 0.f);
    h1 = fmaxf(h1 * L1 + LB1, 0.f);
    h0 = fmaxf(h0 * L2 + LB2, 0.f);
    h1 = fmaxf(h1 * L2 + LB2, 0.f);

    for (int o = 16; o > 0; o >>= 1) {
        h0 += __shfl_xor_sync(0xFFFFFFFFu, h0, o);
        h1 += __shfl_xor_sync(0xFFFFFFFFu, h1, o);
    }
    int warp = threadIdx.x >> 5;
    int lane = threadIdx.x & 31;
    if (lane == 0) { red0[warp] = h0; red1[warp] = h1; }
    __syncthreads();

    if (threadIdx.x == 0) {
        float t0 = 0.f, t1 = 0.f;
        #pragma unroll
        for (int w = 0; w < 8; ++w) { t0 += red0[w]; t1 += red1[w]; }
        atomicAdd(&g_sums[0], t0);
        atomicAdd(&g_sums[1], t1);
        __threadfence();
        unsigned int prev = atomicAdd(&g_done, 1u);
        last = (prev == gridDim.x - 1);
    }
    __syncthreads();

    if (!last) return;

    // ---- last block: final scalar, then restore state for next replay ----
    if (threadIdx.x == 0 && out_size > BB * NN) {
        const float inv_n = 1.0f / (float)NN;
        float m0 = fmaxf(g_sums[0] * inv_n * w2[0] + b2[0], 0.f);
        float m1 = fmaxf(g_sums[1] * inv_n * w2[0] + b2[0], 0.f);
        float s0v = fmaxf(m0 * w3[0] + b3[0], 0.f);
        float s1v = fmaxf(m1 * w3[0] + b3[0], 0.f);
        float v   = fmaxf(s0v, s1v);
        out[BB * NN] = v * wv[0] + bv[0];
    }

    // Self-clean: every block has finished reading g_deg/g_sums (their reads
    // precede their g_done bump). Next launch in the stream can't start
    // until this kernel fully retires, so no fences needed here.
    float4 z4 = make_float4(0.f, 0.f, 0.f, 0.f);
    #pragma unroll
    for (int i = threadIdx.x; i < NN / 4; i += 256)
        ((float4*)g_deg)[i] = z4;
    if (threadIdx.x == 0) {
        g_sums[0] = 0.0f;
        g_sums[1] = 0.0f;
        g_done = 0u;
    }
}

// ---------------------------------------------------------------------------
extern "C" void kernel_launch(void* const* d_in, const int* in_sizes, int n_in,
                              void* d_out, int out_size) {
    const float* x   = (const float*)d_in[0];
    const float* dsm = (const float*)d_in[1];
    const float* w1  = (const float*)d_in[2];
    const float* b1  = (const float*)d_in[3];
    const float* lw1 = (const float*)d_in[4];
    const float* lb1 = (const float*)d_in[5];
    const float* lw2 = (const float*)d_in[6];
    const float* lb2 = (const float*)d_in[7];
    const float* w2  = (const float*)d_in[8];
    const float* b2  = (const float*)d_in[9];
    const float* w3  = (const float*)d_in[10];
    const float* b3  = (const float*)d_in[11];
    // wa (d_in[12]) / ba (d_in[13]) cancel inside the size-1 softmax
    const float* wv  = (const float*)d_in[14];
    const float* bv  = (const float*)d_in[15];
    float* out = (float*)d_out;

    dim3 grid(GRID_X, GRID_Y);  // (8, 64) = 512 blocks
    colsum_kernel<<<grid, 256>>>(dsm, out, out_size);
    matvec_kernel<<<grid, 256>>>(dsm, x);

    reduce_finalize_kernel<<<NN / 256, 256>>>(w1, b1, lw1, lb1, lw2, lb2,
                                              w2, b2, w3, b3, wv, bv, out, out_size);
}